// round 4
// baseline (speedup 1.0000x reference)
#include <cuda_runtime.h>

#define Bsz 64
#define Tn  16384
#define H1n 64
#define H2n 8
#define RING 64
#define RSTR 9   // ring row stride -> conflict-free LDS across lanes

typedef unsigned long long u64;

__device__ __forceinline__ u64 pk2(float lo, float hi) {
    u64 r; asm("mov.b64 %0, {%1,%2};" : "=l"(r) : "f"(lo), "f"(hi)); return r;
}
__device__ __forceinline__ float2 upk2(u64 v) {
    float2 f; asm("mov.b64 {%0,%1}, %2;" : "=f"(f.x), "=f"(f.y) : "l"(v)); return f;
}
__device__ __forceinline__ void fma2(u64 &d, u64 a, u64 b) {
    asm("fma.rn.f32x2 %0, %1, %2, %0;" : "+l"(d) : "l"(a), "l"(b));
}
__device__ __forceinline__ void add2(u64 &d, u64 a) {
    asm("add.rn.f32x2 %0, %0, %1;" : "+l"(d) : "l"(a));
}
__device__ __forceinline__ float tanh_(float v) {
    float r; asm("tanh.approx.f32 %0, %1;" : "=f"(r) : "f"(v)); return r;
}
__device__ __forceinline__ float sigm(float v) {
    return fmaf(0.5f, tanh_(0.5f * v), 0.5f);
}

// One block per batch row. 18 warps:
//   warps 0-15 : layer-1, K-split. Warp w owns cells [4w,4w+4).
//                lane = cellLocal*8 + gate*2 + khalf. Each lane: 32-long
//                half-dot (8 LDS.128 + 16 fma2, depth 4) + shfl_xor combine.
//                kh=1 lanes rotate their chunk order by 4 -> disjoint banks.
//   warp 16    : layer-2 state (h2,c2), one step behind; h2 -> smem ring.
//   warp 17    : batched output projection from the ring (off-path).
__global__ void __launch_bounds__(576, 1) lstm2_kernel(
    const float* __restrict__ x,
    const float* __restrict__ Wih1,
    const float* __restrict__ Whh1,
    const float* __restrict__ b1,
    const float* __restrict__ Wih2,
    const float* __restrict__ Whh2,
    const float* __restrict__ b2,
    const float* __restrict__ Wout,
    const float* __restrict__ bout,
    float* __restrict__ out)
{
    const int b    = blockIdx.x;
    const int tid  = threadIdx.x;
    const int wid  = tid >> 5;
    const int lane = tid & 31;

    __shared__ __align__(16) float h1buf[2][H1n];
    __shared__ float h2ring[RING * RSTR];

    const float* xb = x + (size_t)b * Tn;
    float*       yb = out + (size_t)b * Tn;

    u64   w[32];                       // L1: 16 used; L2: 32 used
    float wih = 0.f, bias = 0.f;
    float c1 = 0.f, h1v = 0.f;
    float w2h[8];
    float bias2 = 0.f, woutv = 0.f, boutv = 0.f;
    float c2 = 0.f, h2v = 0.f;
    int   cell = 0, q = 0, kh = 0;

    if (wid < 16) {
        cell = wid * 4 + (lane >> 3);
        q    = (lane >> 1) & 3;        // gate
        kh   = lane & 1;               // K-half
        const int row = q * H1n + cell;
        const float* wr = Whh1 + row * H1n + kh * 32;
        #pragma unroll
        for (int k = 0; k < 8; k++) {
            int m = (k + 4 * kh) & 7;  // chunk rotation for kh=1
            w[2 * k]     = pk2(wr[4 * m],     wr[4 * m + 1]);
            w[2 * k + 1] = pk2(wr[4 * m + 2], wr[4 * m + 3]);
        }
        wih  = (kh == 0) ? Wih1[row] : 0.f;
        bias = (kh == 0) ? b1[row]   : 0.f;
        if (tid < H1n) h1buf[0][tid] = 0.0f;
    } else if (wid == 16) {
        cell = lane >> 2;
        q    = lane & 3;
        const int row = q * H2n + cell;
        const float2* wp = (const float2*)(Wih2 + row * H1n);
        #pragma unroll
        for (int k = 0; k < 32; k++) { float2 f = wp[k]; w[k] = pk2(f.x, f.y); }
        #pragma unroll
        for (int k = 0; k < 8; k++) w2h[k] = Whh2[row * H2n + k];
        bias2 = b2[row];
        woutv = Wout[cell];
        boutv = bout[0];
    } else { // wid == 17 : output-projection warp
        #pragma unroll
        for (int k = 0; k < 8; k++) w2h[k] = Wout[k];
        boutv = bout[0];
    }
    __syncthreads();

    float x_cur = xb[0];
    float x_n1  = xb[1];
    int p = 0;

    for (int t = 0; t <= Tn; ++t) {
        if (wid < 16) {
            if (t < Tn) {
                float x_n2 = (t + 2 < Tn) ? xb[t + 2] : 0.0f;
                u64 a0 = pk2(fmaf(x_cur, wih, bias), 0.0f);
                u64 a1 = pk2(0.f, 0.f), a2 = a1, a3 = a1;
                const ulonglong2* hp = (const ulonglong2*)(&h1buf[p][kh * 32]);
                #pragma unroll
                for (int k = 0; k < 8; k += 2) {
                    int m0 = (k + 4 * kh) & 7;
                    int m1 = (k + 1 + 4 * kh) & 7;
                    ulonglong2 ha = hp[m0];
                    ulonglong2 hb = hp[m1];
                    fma2(a0, w[2 * k],     ha.x);
                    fma2(a1, w[2 * k + 1], ha.y);
                    fma2(a2, w[2 * k + 2], hb.x);
                    fma2(a3, w[2 * k + 3], hb.y);
                }
                add2(a0, a1); add2(a2, a3); add2(a0, a2);
                float2 s2 = upk2(a0);
                float gh = s2.x + s2.y;
                float g = gh + __shfl_xor_sync(0xffffffffu, gh, 1);
                float act = (q == 2) ? tanh_(g) : sigm(g);
                const unsigned base = lane & 24u;   // cell base lane
                float ai = __shfl_sync(0xffffffffu, act, base + 0);
                float af = __shfl_sync(0xffffffffu, act, base + 2);
                float ag = __shfl_sync(0xffffffffu, act, base + 4);
                float ao = __shfl_sync(0xffffffffu, act, base + 6);
                c1  = fmaf(af, c1, ai * ag);
                h1v = ao * tanh_(c1);
                if ((lane & 7) == 0) h1buf[p ^ 1][cell] = h1v;
                x_cur = x_n1;
                x_n1  = x_n2;
            }
        } else if (wid == 16) {
            if (t >= 1) {
                const int s = t - 1;
                u64 a0 = pk2(bias2, 0.0f);
                u64 a1 = pk2(0.f, 0.f), a2 = a1, a3 = a1;
                const ulonglong2* hp = (const ulonglong2*)(&h1buf[p][0]);
                #pragma unroll
                for (int k = 0; k < 8; k++) {
                    ulonglong2 ha = hp[2 * k];
                    ulonglong2 hb = hp[2 * k + 1];
                    fma2(a0, w[4 * k + 0], ha.x);
                    fma2(a1, w[4 * k + 1], ha.y);
                    fma2(a2, w[4 * k + 2], hb.x);
                    fma2(a3, w[4 * k + 3], hb.y);
                }
                add2(a0, a1); add2(a2, a3); add2(a0, a2);
                float2 s2 = upk2(a0);
                float g = s2.x + s2.y;
                float r0, r1, r2, r3;
                {
                    float h0 = __shfl_sync(0xffffffffu, h2v, 0);
                    float h1_ = __shfl_sync(0xffffffffu, h2v, 4);
                    float h2_ = __shfl_sync(0xffffffffu, h2v, 8);
                    float h3 = __shfl_sync(0xffffffffu, h2v, 12);
                    float h4 = __shfl_sync(0xffffffffu, h2v, 16);
                    float h5 = __shfl_sync(0xffffffffu, h2v, 20);
                    float h6 = __shfl_sync(0xffffffffu, h2v, 24);
                    float h7 = __shfl_sync(0xffffffffu, h2v, 28);
                    r0 = w2h[0] * h0; r1 = w2h[1] * h1_;
                    r2 = w2h[2] * h2_; r3 = w2h[3] * h3;
                    r0 = fmaf(w2h[4], h4, r0); r1 = fmaf(w2h[5], h5, r1);
                    r2 = fmaf(w2h[6], h6, r2); r3 = fmaf(w2h[7], h7, r3);
                }
                g += (r0 + r1) + (r2 + r3);
                float act = (q == 2) ? tanh_(g) : sigm(g);
                const unsigned bl = lane & ~3u;
                float ai = __shfl_sync(0xffffffffu, act, bl + 0);
                float af = __shfl_sync(0xffffffffu, act, bl + 1);
                float ag = __shfl_sync(0xffffffffu, act, bl + 2);
                float ao = __shfl_sync(0xffffffffu, act, bl + 3);
                c2  = fmaf(af, c2, ai * ag);
                h2v = ao * tanh_(c2);
                if (q == 0) h2ring[(s & (RING - 1)) * RSTR + cell] = h2v;
            }
        } else { // wid == 17 : batched output projection
            if (t >= 32 && (t & 31) == 0) {
                const int s = t - 33 + lane;     // steps [t-33, t-2]
                if (s >= 0) {
                    const float* r = &h2ring[(s & (RING - 1)) * RSTR];
                    float acc0 = boutv, acc1 = 0.f;
                    #pragma unroll
                    for (int k = 0; k < 4; k++) {
                        acc0 = fmaf(r[2 * k],     w2h[2 * k],     acc0);
                        acc1 = fmaf(r[2 * k + 1], w2h[2 * k + 1], acc1);
                    }
                    yb[s] = acc0 + acc1 + xb[s];
                }
            }
        }
        __syncthreads();
        p ^= 1;
    }

    // last y (step Tn-1): warp 16 still holds h2v for it
    if (wid == 16) {
        float prod = h2v * woutv;
        prod += __shfl_xor_sync(0xffffffffu, prod, 4);
        prod += __shfl_xor_sync(0xffffffffu, prod, 8);
        prod += __shfl_xor_sync(0xffffffffu, prod, 16);
        if (lane == 0) yb[Tn - 1] = prod + boutv + xb[Tn - 1];
    }

    // final states: layout  y | h1 | c1 | h2 | c2  (each with leading dim 1)
    const int OH1 = Bsz * Tn;
    const int OC1 = OH1 + Bsz * H1n;
    const int OH2 = OC1 + Bsz * H1n;
    const int OC2 = OH2 + Bsz * H2n;
    if (wid < 16) {
        if ((lane & 7) == 0) {
            out[OH1 + b * H1n + cell] = h1v;
            out[OC1 + b * H1n + cell] = c1;
        }
    } else if (wid == 16) {
        if (q == 0) {
            out[OH2 + b * H2n + cell] = h2v;
            out[OC2 + b * H2n + cell] = c2;
        }
    }
}

extern "C" void kernel_launch(void* const* d_in, const int* in_sizes, int n_in,
                              void* d_out, int out_size) {
    const float* x     = (const float*)d_in[0];
    const float* Wih1  = (const float*)d_in[1];
    const float* Whh1  = (const float*)d_in[2];
    const float* b1    = (const float*)d_in[3];
    const float* Wih2  = (const float*)d_in[4];
    const float* Whh2  = (const float*)d_in[5];
    const float* b2    = (const float*)d_in[6];
    const float* Wout  = (const float*)d_in[7];
    const float* bout  = (const float*)d_in[8];
    float* out = (float*)d_out;

    lstm2_kernel<<<Bsz, 576>>>(x, Wih1, Whh1, b1, Wih2, Whh2, b2, Wout, bout, out);
}

// round 5
// speedup vs baseline: 1.4823x; 1.4823x over previous
#include <cuda_runtime.h>

#define Bsz 64
#define Tn  16384
#define H1n 64
#define H2n 8
#define RING 64
#define RSTR 9   // ring row stride -> conflict-free LDS across lanes

typedef unsigned long long u64;

__device__ __forceinline__ u64 pk2(float lo, float hi) {
    u64 r; asm("mov.b64 %0, {%1,%2};" : "=l"(r) : "f"(lo), "f"(hi)); return r;
}
__device__ __forceinline__ float2 upk2(u64 v) {
    float2 f; asm("mov.b64 {%0,%1}, %2;" : "=f"(f.x), "=f"(f.y) : "l"(v)); return f;
}
__device__ __forceinline__ void fma2(u64 &d, u64 a, u64 b) {
    asm("fma.rn.f32x2 %0, %1, %2, %0;" : "+l"(d) : "l"(a), "l"(b));
}
__device__ __forceinline__ void add2(u64 &d, u64 a) {
    asm("add.rn.f32x2 %0, %0, %1;" : "+l"(d) : "l"(a));
}
__device__ __forceinline__ float tanh_(float v) {
    float r; asm("tanh.approx.f32 %0, %1;" : "=f"(r) : "f"(v)); return r;
}
__device__ __forceinline__ float sigm(float v) {
    return fmaf(0.5f, tanh_(0.5f * v), 0.5f);
}

// One block per batch row. 10 warps:
//   warps 0-7 : layer-1, lane = cellLocal*4 + gate, 8 cells/warp, full 64-dot.
//   warp 8    : layer-2 update (lags 2 steps): K[0:32) half-dot + smem partial
//               from warp 9 + recurrence + activations; h2 -> smem ring.
//   warp 9    : layer-2 K[32:64) partial (lags 1 step, pipelined into warp 8
//               via double-buffered pbuf) + batched output projection.
// h1 kept in a depth-4 smem ring so warp 8 can lag 2 steps safely.
// One __syncthreads per timestep orders everything.
__global__ void __launch_bounds__(320, 1) lstm2_kernel(
    const float* __restrict__ x,
    const float* __restrict__ Wih1,
    const float* __restrict__ Whh1,
    const float* __restrict__ b1,
    const float* __restrict__ Wih2,
    const float* __restrict__ Whh2,
    const float* __restrict__ b2,
    const float* __restrict__ Wout,
    const float* __restrict__ bout,
    float* __restrict__ out)
{
    const int b    = blockIdx.x;
    const int tid  = threadIdx.x;
    const int wid  = tid >> 5;
    const int lane = tid & 31;

    __shared__ __align__(16) float h1ring[4][H1n];
    __shared__ float pbuf[2][32];      // layer-2 K-high partials (per row)
    __shared__ float h2ring[RING * RSTR];

    const float* xb = x + (size_t)b * Tn;
    float*       yb = out + (size_t)b * Tn;

    u64   w[32];                       // L1: 32 used; L2 warps: 16 used
    float wih = 0.f, bias = 0.f;
    float c1 = 0.f, h1v = 0.f;
    float w2h[8];
    float bias2 = 0.f, boutv = 0.f;
    float c2 = 0.f, h2v = 0.f;
    int   cell = 0, q = 0;

    if (wid < 8) {
        cell = wid * 8 + (lane >> 2);
        q    = lane & 3;
        const int row = q * H1n + cell;
        const float2* wp = (const float2*)(Whh1 + row * H1n);
        #pragma unroll
        for (int k = 0; k < 32; k++) { float2 f = wp[k]; w[k] = pk2(f.x, f.y); }
        wih  = Wih1[row];
        bias = b1[row];
        if (tid < H1n) h1ring[3][tid] = 0.0f;   // h1[-1] = 0
    } else if (wid == 8) {
        cell = lane >> 2;
        q    = lane & 3;
        const int row = q * H2n + cell;
        const float2* wp = (const float2*)(Wih2 + row * H1n);   // K[0:32)
        #pragma unroll
        for (int k = 0; k < 16; k++) { float2 f = wp[k]; w[k] = pk2(f.x, f.y); }
        #pragma unroll
        for (int k = 0; k < 8; k++) w2h[k] = Whh2[row * H2n + k];
        bias2 = b2[row];
    } else { // wid == 9 : layer-2 K-high partial + output projection
        cell = lane >> 2;
        q    = lane & 3;
        const int row = q * H2n + cell;
        const float2* wp = (const float2*)(Wih2 + row * H1n + 32); // K[32:64)
        #pragma unroll
        for (int k = 0; k < 16; k++) { float2 f = wp[k]; w[k] = pk2(f.x, f.y); }
        #pragma unroll
        for (int k = 0; k < 8; k++) w2h[k] = Wout[k];
        boutv = bout[0];
    }
    __syncthreads();

    float x_cur = xb[0];
    float x_n1  = xb[1];

    for (int t = 0; t <= Tn + 1; ++t) {
        if (wid < 8) {
            if (t < Tn) {
                float x_n2 = (t + 2 < Tn) ? xb[t + 2] : 0.0f;
                u64 a0 = pk2(fmaf(x_cur, wih, bias), 0.0f);
                u64 a1 = pk2(0.f, 0.f), a2 = a1, a3 = a1;
                const ulonglong2* hp = (const ulonglong2*)(&h1ring[(t + 3) & 3][0]);
                #pragma unroll
                for (int k = 0; k < 8; k++) {
                    ulonglong2 ha = hp[2 * k];
                    ulonglong2 hb = hp[2 * k + 1];
                    fma2(a0, w[4 * k + 0], ha.x);
                    fma2(a1, w[4 * k + 1], ha.y);
                    fma2(a2, w[4 * k + 2], hb.x);
                    fma2(a3, w[4 * k + 3], hb.y);
                }
                add2(a0, a1); add2(a2, a3); add2(a0, a2);
                float2 s2 = upk2(a0);
                float g = s2.x + s2.y;
                float act = (q == 2) ? tanh_(g) : sigm(g);
                const unsigned bl = lane & ~3u;
                float ai = __shfl_sync(0xffffffffu, act, bl + 0);
                float af = __shfl_sync(0xffffffffu, act, bl + 1);
                float ag = __shfl_sync(0xffffffffu, act, bl + 2);
                float ao = __shfl_sync(0xffffffffu, act, bl + 3);
                c1  = fmaf(af, c1, ai * ag);
                h1v = ao * tanh_(c1);
                if (q == 0) h1ring[t & 3][cell] = h1v;
                x_cur = x_n1;
                x_n1  = x_n2;
            }
        } else if (wid == 8) {
            if (t >= 2) {
                const int s = t - 2;
                // K-low half dot of h1[s]
                u64 a0 = pk2(bias2, 0.0f);
                u64 a1 = pk2(0.f, 0.f);
                const ulonglong2* hp = (const ulonglong2*)(&h1ring[s & 3][0]);
                #pragma unroll
                for (int k = 0; k < 4; k++) {
                    ulonglong2 ha = hp[2 * k];
                    ulonglong2 hb = hp[2 * k + 1];
                    fma2(a0, w[4 * k + 0], ha.x);
                    fma2(a1, w[4 * k + 1], ha.y);
                    fma2(a0, w[4 * k + 2], hb.x);
                    fma2(a1, w[4 * k + 3], hb.y);
                }
                add2(a0, a1);
                float2 s2 = upk2(a0);
                // K-high partial from warp 9 (written at iter s+1 = t-1)
                float g = s2.x + s2.y + pbuf[(t - 1) & 1][lane];
                // h2 recurrence: 4 accumulators, serial depth 2
                float r0, r1, r2, r3;
                {
                    float h0 = __shfl_sync(0xffffffffu, h2v, 0);
                    float h1_ = __shfl_sync(0xffffffffu, h2v, 4);
                    float h2_ = __shfl_sync(0xffffffffu, h2v, 8);
                    float h3 = __shfl_sync(0xffffffffu, h2v, 12);
                    float h4 = __shfl_sync(0xffffffffu, h2v, 16);
                    float h5 = __shfl_sync(0xffffffffu, h2v, 20);
                    float h6 = __shfl_sync(0xffffffffu, h2v, 24);
                    float h7 = __shfl_sync(0xffffffffu, h2v, 28);
                    r0 = w2h[0] * h0; r1 = w2h[1] * h1_;
                    r2 = w2h[2] * h2_; r3 = w2h[3] * h3;
                    r0 = fmaf(w2h[4], h4, r0); r1 = fmaf(w2h[5], h5, r1);
                    r2 = fmaf(w2h[6], h6, r2); r3 = fmaf(w2h[7], h7, r3);
                }
                g += (r0 + r1) + (r2 + r3);
                float act = (q == 2) ? tanh_(g) : sigm(g);
                const unsigned bl = lane & ~3u;
                float ai = __shfl_sync(0xffffffffu, act, bl + 0);
                float af = __shfl_sync(0xffffffffu, act, bl + 1);
                float ag = __shfl_sync(0xffffffffu, act, bl + 2);
                float ao = __shfl_sync(0xffffffffu, act, bl + 3);
                c2  = fmaf(af, c2, ai * ag);
                h2v = ao * tanh_(c2);
                if (q == 0) h2ring[(s & (RING - 1)) * RSTR + cell] = h2v;
            }
        } else { // wid == 9
            if (t >= 1 && t <= Tn) {
                const int s = t - 1;
                // K-high half dot of h1[s] -> pbuf
                u64 a0 = pk2(0.f, 0.f), a1 = a0;
                const ulonglong2* hp = (const ulonglong2*)(&h1ring[s & 3][32]);
                #pragma unroll
                for (int k = 0; k < 4; k++) {
                    ulonglong2 ha = hp[2 * k];
                    ulonglong2 hb = hp[2 * k + 1];
                    fma2(a0, w[4 * k + 0], ha.x);
                    fma2(a1, w[4 * k + 1], ha.y);
                    fma2(a0, w[4 * k + 2], hb.x);
                    fma2(a1, w[4 * k + 3], hb.y);
                }
                add2(a0, a1);
                float2 s2 = upk2(a0);
                pbuf[t & 1][lane] = s2.x + s2.y;
            }
            // batched output projection: h2[s2] is in the ring once iter s2+2
            // has completed, so at iter t we may read s2 <= t-3.
            if ((t & 31) == 0 && t >= 32) {
                const int s2i = t - 34 + lane;   // window [t-34, t-3]
                if (s2i >= 0) {
                    const float* r = &h2ring[(s2i & (RING - 1)) * RSTR];
                    float acc0 = boutv, acc1 = 0.f;
                    #pragma unroll
                    for (int k = 0; k < 4; k++) {
                        acc0 = fmaf(r[2 * k],     w2h[2 * k],     acc0);
                        acc1 = fmaf(r[2 * k + 1], w2h[2 * k + 1], acc1);
                    }
                    yb[s2i] = acc0 + acc1 + xb[s2i];
                }
            }
        }
        __syncthreads();
    }

    // tail: y for the last two steps (s = Tn-2, Tn-1) from the ring
    if (wid == 9 && lane < 2) {
        const int s2i = Tn - 2 + lane;
        const float* r = &h2ring[(s2i & (RING - 1)) * RSTR];
        float acc0 = boutv, acc1 = 0.f;
        #pragma unroll
        for (int k = 0; k < 4; k++) {
            acc0 = fmaf(r[2 * k],     w2h[2 * k],     acc0);
            acc1 = fmaf(r[2 * k + 1], w2h[2 * k + 1], acc1);
        }
        yb[s2i] = acc0 + acc1 + xb[s2i];
    }

    // final states: layout  y | h1 | c1 | h2 | c2  (each with leading dim 1)
    const int OH1 = Bsz * Tn;
    const int OC1 = OH1 + Bsz * H1n;
    const int OH2 = OC1 + Bsz * H1n;
    const int OC2 = OH2 + Bsz * H2n;
    if (wid < 8) {
        if (q == 0) {
            out[OH1 + b * H1n + cell] = h1v;
            out[OC1 + b * H1n + cell] = c1;
        }
    } else if (wid == 8) {
        if (q == 0) {
            out[OH2 + b * H2n + cell] = h2v;
            out[OC2 + b * H2n + cell] = c2;
        }
    }
}

extern "C" void kernel_launch(void* const* d_in, const int* in_sizes, int n_in,
                              void* d_out, int out_size) {
    const float* x     = (const float*)d_in[0];
    const float* Wih1  = (const float*)d_in[1];
    const float* Whh1  = (const float*)d_in[2];
    const float* b1    = (const float*)d_in[3];
    const float* Wih2  = (const float*)d_in[4];
    const float* Whh2  = (const float*)d_in[5];
    const float* b2    = (const float*)d_in[6];
    const float* Wout  = (const float*)d_in[7];
    const float* bout  = (const float*)d_in[8];
    float* out = (float*)d_out;

    lstm2_kernel<<<Bsz, 320>>>(x, Wih1, Whh1, b1, Wih2, Whh2, b2, Wout, bout, out);
}

// round 6
// speedup vs baseline: 1.5564x; 1.0500x over previous
#include <cuda_runtime.h>

#define Bsz 64
#define Tn  16384
#define H1n 64
#define H2n 8
#define RING 64
#define RSTR 9   // ring row stride -> conflict-free LDS across lanes

typedef unsigned long long u64;

__device__ __forceinline__ u64 pk2(float lo, float hi) {
    u64 r; asm("mov.b64 %0, {%1,%2};" : "=l"(r) : "f"(lo), "f"(hi)); return r;
}
__device__ __forceinline__ float2 upk2(u64 v) {
    float2 f; asm("mov.b64 {%0,%1}, %2;" : "=f"(f.x), "=f"(f.y) : "l"(v)); return f;
}
__device__ __forceinline__ void fma2(u64 &d, u64 a, u64 b) {
    asm("fma.rn.f32x2 %0, %1, %2, %0;" : "+l"(d) : "l"(a), "l"(b));
}
__device__ __forceinline__ void add2(u64 &d, u64 a) {
    asm("add.rn.f32x2 %0, %0, %1;" : "+l"(d) : "l"(a));
}
__device__ __forceinline__ float tanh_(float v) {
    float r; asm("tanh.approx.f32 %0, %1;" : "=f"(r) : "f"(v)); return r;
}
__device__ __forceinline__ float sigm(float v) {
    return fmaf(0.5f, tanh_(0.5f * v), 0.5f);
}

// One block per batch row. 12 warps:
//   warps 0-7  : layer-1, lane = cellLocal*4 + gate, 8 cells/warp, 64-dot.
//   warp 8     : layer-2 update only (lags 2): sums 3 smem partials +
//                recurrence + activations; h2 -> smem ring.  (SMSP0)
//   warps 9-11 : layer-2 input dot Wih2@h1[t-1], K-split 24/24/16, one step
//                ahead of warp 8, partials into double-buffered pbuf.
//                (SMSP1/2/3).  Warp 11 also does batched output projection.
// h1 in a depth-4 smem ring; one __syncthreads per step orders all hand-offs.
__global__ void __launch_bounds__(384, 1) lstm2_kernel(
    const float* __restrict__ x,
    const float* __restrict__ Wih1,
    const float* __restrict__ Whh1,
    const float* __restrict__ b1,
    const float* __restrict__ Wih2,
    const float* __restrict__ Whh2,
    const float* __restrict__ b2,
    const float* __restrict__ Wout,
    const float* __restrict__ bout,
    float* __restrict__ out)
{
    const int b    = blockIdx.x;
    const int tid  = threadIdx.x;
    const int wid  = tid >> 5;
    const int lane = tid & 31;

    __shared__ __align__(16) float h1ring[4][H1n];
    __shared__ float pbuf[2][3][32];   // [phase][src warp 9/10/11][row]
    __shared__ float h2ring[RING * RSTR];

    const float* xb = x + (size_t)b * Tn;
    float*       yb = out + (size_t)b * Tn;

    u64   w[32];                       // L1: 32 used; helpers: <=12 used
    float wih = 0.f, bias = 0.f;
    float c1 = 0.f, h1v = 0.f;
    float w2h[8];
    float bias2 = 0.f, boutv = 0.f;
    float c2 = 0.f, h2v = 0.f;
    int   cell = 0, q = 0;

    if (wid < 8) {
        cell = wid * 8 + (lane >> 2);
        q    = lane & 3;
        const int row = q * H1n + cell;
        const float2* wp = (const float2*)(Whh1 + row * H1n);
        #pragma unroll
        for (int k = 0; k < 32; k++) { float2 f = wp[k]; w[k] = pk2(f.x, f.y); }
        wih  = Wih1[row];
        bias = b1[row];
        if (tid < H1n) h1ring[3][tid] = 0.0f;   // h1[-1] = 0
    } else if (wid == 8) {
        cell = lane >> 2;
        q    = lane & 3;
        const int row = q * H2n + cell;
        #pragma unroll
        for (int k = 0; k < 8; k++) w2h[k] = Whh2[row * H2n + k];
    } else { // wid 9..11 : K-split input-dot helpers
        cell = lane >> 2;
        q    = lane & 3;
        const int row = q * H2n + cell;
        const int koff = (wid == 9) ? 0 : (wid == 10) ? 24 : 48;
        const int kcnt = (wid == 11) ? 16 : 24;       // floats
        const float2* wp = (const float2*)(Wih2 + row * H1n + koff);
        for (int k = 0; k < kcnt / 2; k++) { float2 f = wp[k]; w[k] = pk2(f.x, f.y); }
        bias2 = (wid == 9) ? b2[row] : 0.f;
        if (wid == 11) {
            #pragma unroll
            for (int k = 0; k < 8; k++) w2h[k] = Wout[k];
            boutv = bout[0];
        }
    }
    __syncthreads();

    float x_cur = xb[0];
    float x_n1  = xb[1];

    for (int t = 0; t <= Tn + 1; ++t) {
        if (wid < 8) {
            if (t < Tn) {
                float x_n2 = (t + 2 < Tn) ? xb[t + 2] : 0.0f;
                u64 a0 = pk2(fmaf(x_cur, wih, bias), 0.0f);
                u64 a1 = pk2(0.f, 0.f), a2 = a1, a3 = a1;
                const ulonglong2* hp = (const ulonglong2*)(&h1ring[(t + 3) & 3][0]);
                #pragma unroll
                for (int k = 0; k < 8; k++) {
                    ulonglong2 ha = hp[2 * k];
                    ulonglong2 hb = hp[2 * k + 1];
                    fma2(a0, w[4 * k + 0], ha.x);
                    fma2(a1, w[4 * k + 1], ha.y);
                    fma2(a2, w[4 * k + 2], hb.x);
                    fma2(a3, w[4 * k + 3], hb.y);
                }
                add2(a0, a1); add2(a2, a3); add2(a0, a2);
                float2 s2 = upk2(a0);
                float g = s2.x + s2.y;
                float act = (q == 2) ? tanh_(g) : sigm(g);
                const unsigned bl = lane & ~3u;
                float ai = __shfl_sync(0xffffffffu, act, bl + 0);
                float af = __shfl_sync(0xffffffffu, act, bl + 1);
                float ag = __shfl_sync(0xffffffffu, act, bl + 2);
                float ao = __shfl_sync(0xffffffffu, act, bl + 3);
                c1  = fmaf(af, c1, ai * ag);
                h1v = ao * tanh_(c1);
                if (q == 0) h1ring[t & 3][cell] = h1v;
                x_cur = x_n1;
                x_n1  = x_n2;
            }
        } else if (wid == 8) {
            if (t >= 2) {
                const int s = t - 2;
                const int ph = (t - 1) & 1;
                // gate pre-activation from the 3 helper partials
                float g = (pbuf[ph][0][lane] + pbuf[ph][1][lane]) + pbuf[ph][2][lane];
                // h2 recurrence: 4 accumulators, serial depth 2
                float r0, r1, r2, r3;
                {
                    float h0 = __shfl_sync(0xffffffffu, h2v, 0);
                    float h1_ = __shfl_sync(0xffffffffu, h2v, 4);
                    float h2_ = __shfl_sync(0xffffffffu, h2v, 8);
                    float h3 = __shfl_sync(0xffffffffu, h2v, 12);
                    float h4 = __shfl_sync(0xffffffffu, h2v, 16);
                    float h5 = __shfl_sync(0xffffffffu, h2v, 20);
                    float h6 = __shfl_sync(0xffffffffu, h2v, 24);
                    float h7 = __shfl_sync(0xffffffffu, h2v, 28);
                    r0 = w2h[0] * h0; r1 = w2h[1] * h1_;
                    r2 = w2h[2] * h2_; r3 = w2h[3] * h3;
                    r0 = fmaf(w2h[4], h4, r0); r1 = fmaf(w2h[5], h5, r1);
                    r2 = fmaf(w2h[6], h6, r2); r3 = fmaf(w2h[7], h7, r3);
                }
                g += (r0 + r1) + (r2 + r3);
                float act = (q == 2) ? tanh_(g) : sigm(g);
                const unsigned bl = lane & ~3u;
                float ai = __shfl_sync(0xffffffffu, act, bl + 0);
                float af = __shfl_sync(0xffffffffu, act, bl + 1);
                float ag = __shfl_sync(0xffffffffu, act, bl + 2);
                float ao = __shfl_sync(0xffffffffu, act, bl + 3);
                c2  = fmaf(af, c2, ai * ag);
                h2v = ao * tanh_(c2);
                if (q == 0) h2ring[(s & (RING - 1)) * RSTR + cell] = h2v;
            }
        } else { // wid 9..11 : layer-2 input-dot partials (for step s = t-1)
            if (t >= 1 && t <= Tn) {
                const int s = t - 1;
                u64 a0 = pk2(bias2, 0.0f), a1 = pk2(0.f, 0.f);
                if (wid == 9) {
                    const ulonglong2* hp = (const ulonglong2*)(&h1ring[s & 3][0]);
                    #pragma unroll
                    for (int k = 0; k < 3; k++) {
                        ulonglong2 ha = hp[2 * k];
                        ulonglong2 hb = hp[2 * k + 1];
                        fma2(a0, w[4 * k + 0], ha.x);
                        fma2(a1, w[4 * k + 1], ha.y);
                        fma2(a0, w[4 * k + 2], hb.x);
                        fma2(a1, w[4 * k + 3], hb.y);
                    }
                } else if (wid == 10) {
                    const ulonglong2* hp = (const ulonglong2*)(&h1ring[s & 3][24]);
                    #pragma unroll
                    for (int k = 0; k < 3; k++) {
                        ulonglong2 ha = hp[2 * k];
                        ulonglong2 hb = hp[2 * k + 1];
                        fma2(a0, w[4 * k + 0], ha.x);
                        fma2(a1, w[4 * k + 1], ha.y);
                        fma2(a0, w[4 * k + 2], hb.x);
                        fma2(a1, w[4 * k + 3], hb.y);
                    }
                } else {
                    const ulonglong2* hp = (const ulonglong2*)(&h1ring[s & 3][48]);
                    #pragma unroll
                    for (int k = 0; k < 2; k++) {
                        ulonglong2 ha = hp[2 * k];
                        ulonglong2 hb = hp[2 * k + 1];
                        fma2(a0, w[4 * k + 0], ha.x);
                        fma2(a1, w[4 * k + 1], ha.y);
                        fma2(a0, w[4 * k + 2], hb.x);
                        fma2(a1, w[4 * k + 3], hb.y);
                    }
                }
                add2(a0, a1);
                float2 s2 = upk2(a0);
                pbuf[t & 1][wid - 9][lane] = s2.x + s2.y;
            }
            // batched output projection on warp 11 (h2[s2] ready for s2 <= t-3)
            if (wid == 11 && (t & 31) == 0 && t >= 32) {
                const int s2i = t - 34 + lane;   // window [t-34, t-3]
                if (s2i >= 0) {
                    const float* r = &h2ring[(s2i & (RING - 1)) * RSTR];
                    float acc0 = boutv, acc1 = 0.f;
                    #pragma unroll
                    for (int k = 0; k < 4; k++) {
                        acc0 = fmaf(r[2 * k],     w2h[2 * k],     acc0);
                        acc1 = fmaf(r[2 * k + 1], w2h[2 * k + 1], acc1);
                    }
                    yb[s2i] = acc0 + acc1 + xb[s2i];
                }
            }
        }
        __syncthreads();
    }

    // tail: y for the last two steps (s = Tn-2, Tn-1) from the ring
    if (wid == 11 && lane < 2) {
        const int s2i = Tn - 2 + lane;
        const float* r = &h2ring[(s2i & (RING - 1)) * RSTR];
        float acc0 = boutv, acc1 = 0.f;
        #pragma unroll
        for (int k = 0; k < 4; k++) {
            acc0 = fmaf(r[2 * k],     w2h[2 * k],     acc0);
            acc1 = fmaf(r[2 * k + 1], w2h[2 * k + 1], acc1);
        }
        yb[s2i] = acc0 + acc1 + xb[s2i];
    }

    // final states: layout  y | h1 | c1 | h2 | c2  (each with leading dim 1)
    const int OH1 = Bsz * Tn;
    const int OC1 = OH1 + Bsz * H1n;
    const int OH2 = OC1 + Bsz * H1n;
    const int OC2 = OH2 + Bsz * H2n;
    if (wid < 8) {
        if (q == 0) {
            out[OH1 + b * H1n + cell] = h1v;
            out[OC1 + b * H1n + cell] = c1;
        }
    } else if (wid == 8) {
        if (q == 0) {
            out[OH2 + b * H2n + cell] = h2v;
            out[OC2 + b * H2n + cell] = c2;
        }
    }
}

extern "C" void kernel_launch(void* const* d_in, const int* in_sizes, int n_in,
                              void* d_out, int out_size) {
    const float* x     = (const float*)d_in[0];
    const float* Wih1  = (const float*)d_in[1];
    const float* Whh1  = (const float*)d_in[2];
    const float* b1    = (const float*)d_in[3];
    const float* Wih2  = (const float*)d_in[4];
    const float* Whh2  = (const float*)d_in[5];
    const float* b2    = (const float*)d_in[6];
    const float* Wout  = (const float*)d_in[7];
    const float* bout  = (const float*)d_in[8];
    float* out = (float*)d_out;

    lstm2_kernel<<<Bsz, 384>>>(x, Wih1, Whh1, b1, Wih2, Whh2, b2, Wout, bout, out);
}

// round 7
// speedup vs baseline: 1.6901x; 1.0859x over previous
#include <cuda_runtime.h>

#define Bsz 64
#define Tn  16384
#define H1n 64
#define H2n 8
#define RING 64
#define RSTR 9   // ring row stride -> conflict-free LDS across lanes

typedef unsigned long long u64;

__device__ __forceinline__ u64 pk2(float lo, float hi) {
    u64 r; asm("mov.b64 %0, {%1,%2};" : "=l"(r) : "f"(lo), "f"(hi)); return r;
}
__device__ __forceinline__ float2 upk2(u64 v) {
    float2 f; asm("mov.b64 {%0,%1}, %2;" : "=f"(f.x), "=f"(f.y) : "l"(v)); return f;
}
__device__ __forceinline__ void fma2(u64 &d, u64 a, u64 b) {
    asm("fma.rn.f32x2 %0, %1, %2, %0;" : "+l"(d) : "l"(a), "l"(b));
}
__device__ __forceinline__ void add2(u64 &d, u64 a) {
    asm("add.rn.f32x2 %0, %0, %1;" : "+l"(d) : "l"(a));
}
__device__ __forceinline__ float tanh_(float v) {
    float r; asm("tanh.approx.f32 %0, %1;" : "=f"(r) : "f"(v)); return r;
}
__device__ __forceinline__ float sigm(float v) {
    return fmaf(0.5f, tanh_(0.5f * v), 0.5f);
}

// One block per batch row. 12 warps:
//   warps 0-7  : layer-1, lane = cellLocal*4 + gate, 8 cells/warp, 64-dot.
//   warp 8     : layer-2 update (lags 2), ONE LANE PER CELL (lanes 0-7):
//                all 4 gates in-lane; pbuf partials via float4 LDS; h2(t-1)
//                via small smem double buffer (no shfl on the chain).
//   warps 9-11 : layer-2 input dot Wih2@h1[t-1], K-split 24/24/16, one step
//                ahead of warp 8, partials into double-buffered pbuf.
//                Warp 11 also does the batched output projection.
// h1 in a depth-4 smem ring; one __syncthreads per step orders hand-offs.
__global__ void __launch_bounds__(384, 1) lstm2_kernel(
    const float* __restrict__ x,
    const float* __restrict__ Wih1,
    const float* __restrict__ Whh1,
    const float* __restrict__ b1,
    const float* __restrict__ Wih2,
    const float* __restrict__ Whh2,
    const float* __restrict__ b2,
    const float* __restrict__ Wout,
    const float* __restrict__ bout,
    float* __restrict__ out)
{
    const int b    = blockIdx.x;
    const int tid  = threadIdx.x;
    const int wid  = tid >> 5;
    const int lane = tid & 31;

    __shared__ __align__(16) float h1ring[4][H1n];
    __shared__ __align__(16) float pbuf[2][3][32];   // [phase][src][cell*4+gate]
    __shared__ __align__(16) float h2s[2][H2n];      // h2 double buffer
    __shared__ float h2ring[RING * RSTR];

    const float* xb = x + (size_t)b * Tn;
    float*       yb = out + (size_t)b * Tn;

    u64   w[32];                       // L1: 32; warp8: 16; helpers: <=12
    float wih = 0.f, bias = 0.f;
    float c1 = 0.f, h1v = 0.f;
    float w2h[8];
    float bias2 = 0.f, boutv = 0.f;
    float c2 = 0.f, h2v = 0.f;
    int   cell = 0, q = 0;

    if (wid < 8) {
        cell = wid * 8 + (lane >> 2);
        q    = lane & 3;
        const int row = q * H1n + cell;
        const float2* wp = (const float2*)(Whh1 + row * H1n);
        #pragma unroll
        for (int k = 0; k < 32; k++) { float2 f = wp[k]; w[k] = pk2(f.x, f.y); }
        wih  = Wih1[row];
        bias = b1[row];
        if (tid < H1n) h1ring[3][tid] = 0.0f;   // h1[-1] = 0
    } else if (wid == 8) {
        // lanes 0-7 active: lane = cell, all 4 gates in-lane
        if (lane < H2n) {
            #pragma unroll
            for (int g = 0; g < 4; g++) {
                const int row = g * H2n + lane;
                const float2* wp = (const float2*)(Whh2 + row * H2n);
                #pragma unroll
                for (int j = 0; j < 4; j++) { float2 f = wp[j]; w[4 * g + j] = pk2(f.x, f.y); }
            }
            h2s[0][lane] = 0.0f;
            h2s[1][lane] = 0.0f;
        }
    } else { // wid 9..11 : K-split input-dot helpers
        cell = lane >> 2;
        q    = lane & 3;
        const int row = q * H2n + cell;
        const int koff = (wid == 9) ? 0 : (wid == 10) ? 24 : 48;
        const int kcnt = (wid == 11) ? 16 : 24;       // floats
        const float2* wp = (const float2*)(Wih2 + row * H1n + koff);
        for (int k = 0; k < kcnt / 2; k++) { float2 f = wp[k]; w[k] = pk2(f.x, f.y); }
        bias2 = (wid == 9) ? b2[row] : 0.f;
        if (wid == 11) {
            #pragma unroll
            for (int k = 0; k < 8; k++) w2h[k] = Wout[k];
            boutv = bout[0];
        }
    }
    __syncthreads();

    float x_cur = xb[0];
    float x_n1  = xb[1];

    #pragma unroll 4
    for (int t = 0; t <= Tn + 1; ++t) {
        if (wid < 8) {
            if (t < Tn) {
                float x_n2 = (t + 2 < Tn) ? xb[t + 2] : 0.0f;
                u64 a0 = pk2(fmaf(x_cur, wih, bias), 0.0f);
                u64 a1 = pk2(0.f, 0.f), a2 = a1, a3 = a1;
                const ulonglong2* hp = (const ulonglong2*)(&h1ring[(t + 3) & 3][0]);
                #pragma unroll
                for (int k = 0; k < 8; k++) {
                    ulonglong2 ha = hp[2 * k];
                    ulonglong2 hb = hp[2 * k + 1];
                    fma2(a0, w[4 * k + 0], ha.x);
                    fma2(a1, w[4 * k + 1], ha.y);
                    fma2(a2, w[4 * k + 2], hb.x);
                    fma2(a3, w[4 * k + 3], hb.y);
                }
                add2(a0, a1); add2(a2, a3); add2(a0, a2);
                float2 s2 = upk2(a0);
                float g = s2.x + s2.y;
                float act = (q == 2) ? tanh_(g) : sigm(g);
                const unsigned bl = lane & ~3u;
                float ai = __shfl_sync(0xffffffffu, act, bl + 0);
                float af = __shfl_sync(0xffffffffu, act, bl + 1);
                float ag = __shfl_sync(0xffffffffu, act, bl + 2);
                float ao = __shfl_sync(0xffffffffu, act, bl + 3);
                c1  = fmaf(af, c1, ai * ag);
                h1v = ao * tanh_(c1);
                if (q == 0) h1ring[t & 3][cell] = h1v;
                x_cur = x_n1;
                x_n1  = x_n2;
            }
        } else if (wid == 8) {
            if (t >= 2 && lane < H2n) {
                const int s  = t - 2;
                const int ph = (t - 1) & 1;
                // gate pre-activations from the 3 helper partials (float4 rows)
                const float4 p0 = *(const float4*)&pbuf[ph][0][lane * 4];
                const float4 p1 = *(const float4*)&pbuf[ph][1][lane * 4];
                const float4 p2 = *(const float4*)&pbuf[ph][2][lane * 4];
                float gi = (p0.x + p1.x) + p2.x;
                float gf = (p0.y + p1.y) + p2.y;
                float gg = (p0.z + p1.z) + p2.z;
                float go = (p0.w + p1.w) + p2.w;
                // h2(t-1): broadcast LDS (written last iteration)
                const u64* hq = (const u64*)&h2s[ph][0];
                u64 h01 = hq[0], h23 = hq[1], h45 = hq[2], h67 = hq[3];
                u64 A = pk2(gi, 0.f), B = pk2(gf, 0.f);
                u64 C = pk2(gg, 0.f), D = pk2(go, 0.f);
                fma2(A, w[0],  h01); fma2(B, w[4],  h01);
                fma2(C, w[8],  h01); fma2(D, w[12], h01);
                fma2(A, w[1],  h23); fma2(B, w[5],  h23);
                fma2(C, w[9],  h23); fma2(D, w[13], h23);
                fma2(A, w[2],  h45); fma2(B, w[6],  h45);
                fma2(C, w[10], h45); fma2(D, w[14], h45);
                fma2(A, w[3],  h67); fma2(B, w[7],  h67);
                fma2(C, w[11], h67); fma2(D, w[15], h67);
                float2 fa = upk2(A), fb = upk2(B), fc = upk2(C), fd = upk2(D);
                float ti = sigm(fa.x + fa.y);
                float tf = sigm(fb.x + fb.y);
                float tg = tanh_(fc.x + fc.y);
                float to = sigm(fd.x + fd.y);
                c2  = fmaf(tf, c2, ti * tg);
                h2v = to * tanh_(c2);
                h2s[t & 1][lane] = h2v;
                h2ring[(s & (RING - 1)) * RSTR + lane] = h2v;
            }
        } else { // wid 9..11 : layer-2 input-dot partials (for step s = t-1)
            if (t >= 1 && t <= Tn) {
                const int s = t - 1;
                u64 a0 = pk2(bias2, 0.0f), a1 = pk2(0.f, 0.f);
                if (wid == 9) {
                    const ulonglong2* hp = (const ulonglong2*)(&h1ring[s & 3][0]);
                    #pragma unroll
                    for (int k = 0; k < 3; k++) {
                        ulonglong2 ha = hp[2 * k];
                        ulonglong2 hb = hp[2 * k + 1];
                        fma2(a0, w[4 * k + 0], ha.x);
                        fma2(a1, w[4 * k + 1], ha.y);
                        fma2(a0, w[4 * k + 2], hb.x);
                        fma2(a1, w[4 * k + 3], hb.y);
                    }
                } else if (wid == 10) {
                    const ulonglong2* hp = (const ulonglong2*)(&h1ring[s & 3][24]);
                    #pragma unroll
                    for (int k = 0; k < 3; k++) {
                        ulonglong2 ha = hp[2 * k];
                        ulonglong2 hb = hp[2 * k + 1];
                        fma2(a0, w[4 * k + 0], ha.x);
                        fma2(a1, w[4 * k + 1], ha.y);
                        fma2(a0, w[4 * k + 2], hb.x);
                        fma2(a1, w[4 * k + 3], hb.y);
                    }
                } else {
                    const ulonglong2* hp = (const ulonglong2*)(&h1ring[s & 3][48]);
                    #pragma unroll
                    for (int k = 0; k < 2; k++) {
                        ulonglong2 ha = hp[2 * k];
                        ulonglong2 hb = hp[2 * k + 1];
                        fma2(a0, w[4 * k + 0], ha.x);
                        fma2(a1, w[4 * k + 1], ha.y);
                        fma2(a0, w[4 * k + 2], hb.x);
                        fma2(a1, w[4 * k + 3], hb.y);
                    }
                }
                add2(a0, a1);
                float2 s2 = upk2(a0);
                pbuf[t & 1][wid - 9][lane] = s2.x + s2.y;
            }
            // batched output projection on warp 11 (h2[s2] ready for s2 <= t-3)
            if (wid == 11 && (t & 31) == 0 && t >= 32) {
                const int s2i = t - 34 + lane;   // window [t-34, t-3]
                if (s2i >= 0) {
                    const float* r = &h2ring[(s2i & (RING - 1)) * RSTR];
                    float acc0 = boutv, acc1 = 0.f;
                    #pragma unroll
                    for (int k = 0; k < 4; k++) {
                        acc0 = fmaf(r[2 * k],     w2h[2 * k],     acc0);
                        acc1 = fmaf(r[2 * k + 1], w2h[2 * k + 1], acc1);
                    }
                    yb[s2i] = acc0 + acc1 + xb[s2i];
                }
            }
        }
        __syncthreads();
    }

    // tail: y for the last two steps (s = Tn-2, Tn-1) from the ring
    if (wid == 11 && lane < 2) {
        const int s2i = Tn - 2 + lane;
        const float* r = &h2ring[(s2i & (RING - 1)) * RSTR];
        float acc0 = boutv, acc1 = 0.f;
        #pragma unroll
        for (int k = 0; k < 4; k++) {
            acc0 = fmaf(r[2 * k],     w2h[2 * k],     acc0);
            acc1 = fmaf(r[2 * k + 1], w2h[2 * k + 1], acc1);
        }
        yb[s2i] = acc0 + acc1 + xb[s2i];
    }

    // final states: layout  y | h1 | c1 | h2 | c2  (each with leading dim 1)
    const int OH1 = Bsz * Tn;
    const int OC1 = OH1 + Bsz * H1n;
    const int OH2 = OC1 + Bsz * H1n;
    const int OC2 = OH2 + Bsz * H2n;
    if (wid < 8) {
        if (q == 0) {
            out[OH1 + b * H1n + cell] = h1v;
            out[OC1 + b * H1n + cell] = c1;
        }
    } else if (wid == 8) {
        if (lane < H2n) {
            out[OH2 + b * H2n + lane] = h2v;
            out[OC2 + b * H2n + lane] = c2;
        }
    }
}

extern "C" void kernel_launch(void* const* d_in, const int* in_sizes, int n_in,
                              void* d_out, int out_size) {
    const float* x     = (const float*)d_in[0];
    const float* Wih1  = (const float*)d_in[1];
    const float* Whh1  = (const float*)d_in[2];
    const float* b1    = (const float*)d_in[3];
    const float* Wih2  = (const float*)d_in[4];
    const float* Whh2  = (const float*)d_in[5];
    const float* b2    = (const float*)d_in[6];
    const float* Wout  = (const float*)d_in[7];
    const float* bout  = (const float*)d_in[8];
    float* out = (float*)d_out;

    lstm2_kernel<<<Bsz, 384>>>(x, Wih1, Whh1, b1, Wih2, Whh2, b2, Wout, bout, out);
}